// round 1
// baseline (speedup 1.0000x reference)
#include <cuda_runtime.h>
#include <math.h>

// Problem constants (from reference)
#define Bsz   8192
#define Ein   256
#define Uh    256
#define Vv    4000
#define INdim 512     // E + E
#define Gdim  768     // 3*U

// Scratch (no cudaMalloc allowed) — static __device__ arrays.
__device__ float g_x [Bsz * INdim];   // concat(features, emb[tokens])  16.8 MB
__device__ float g_gx[Bsz * Gdim];    // gx = x @ gru_kernel + b0       25.2 MB
__device__ float g_y [Bsz * Uh];      // y  = h @ fc1_w + fc1_b          8.4 MB

// ---------------------------------------------------------------------------
// Kernel 0: build x = concat(features[b], emb[token[b]])
// ---------------------------------------------------------------------------
__global__ void build_x_kernel(const int* __restrict__ tok,
                               const float* __restrict__ feat,
                               const float* __restrict__ emb) {
    int b = blockIdx.x;
    int c = threadIdx.x;                   // 0..255
    int t = tok[b];                        // tokens shape [B,1]
    g_x[(size_t)b * INdim + c]        = feat[(size_t)b * Ein + c];
    g_x[(size_t)b * INdim + Ein + c]  = emb[(size_t)t * Ein + c];
}

// ---------------------------------------------------------------------------
// Kernel: GRU gates (h0 == 0, so gh = gru_bias[1] exactly)
//   gx already contains x@K + b0 (bias folded into GEMM epilogue)
//   z = sigmoid(gx_z + b1_z); r = sigmoid(gx_r + b1_r)
//   n = tanh(gx_n + r * b1_n); h = (1-z)*n
// ---------------------------------------------------------------------------
__global__ void gru_gates_kernel(const float* __restrict__ gru_bias,
                                 float* __restrict__ h_out) {
    int b = blockIdx.x;
    int u = threadIdx.x;                   // 0..255
    const float* gx = g_gx + (size_t)b * Gdim;
    const float* b1 = gru_bias + Gdim;     // gru_bias[1]
    float xz = gx[u];
    float xr = gx[Uh + u];
    float xn = gx[2 * Uh + u];
    float z = 1.0f / (1.0f + expf(-(xz + b1[u])));
    float r = 1.0f / (1.0f + expf(-(xr + b1[Uh + u])));
    float n = tanhf(xn + r * b1[2 * Uh + u]);
    h_out[(size_t)b * Uh + u] = (1.0f - z) * n;
}

// ---------------------------------------------------------------------------
// Register-tiled fp32 GEMM: C[M,N] = A[M,K] @ B[K,N] + bias[N]
// BM=128, BN=64, BK=16, 256 threads, 8x4 per-thread microtile.
// Requires: M % BM == 0, K % BK == 0. N handled with bounds checks.
// A, B row-major, 16B-aligned rows (K and N multiples of 4).
// ---------------------------------------------------------------------------
template<int BM, int BN, int BK, int TM, int TN>
__global__ void __launch_bounds__(256)
sgemm_bias_kernel(const float* __restrict__ A,
                  const float* __restrict__ Bm,
                  const float* __restrict__ bias,
                  float* __restrict__ C,
                  int M, int N, int K) {
    __shared__ float As[BK][BM];     // transposed A tile
    __shared__ float Bs[BK][BN];

    const int tid = threadIdx.x;
    const int tx  = tid & 15;        // 0..15  -> N direction (TN=4)
    const int ty  = tid >> 4;        // 0..15  -> M direction (TM=8)
    const int row0 = blockIdx.y * BM;
    const int col0 = blockIdx.x * BN;

    float acc[TM][TN];
#pragma unroll
    for (int i = 0; i < TM; i++)
#pragma unroll
        for (int j = 0; j < TN; j++) acc[i][j] = 0.0f;

    for (int k0 = 0; k0 < K; k0 += BK) {
        // --- load A tile: BM*BK/4 = 512 float4 quads, 2 per thread ---
#pragma unroll
        for (int l = 0; l < 2; l++) {
            int q  = tid + l * 256;          // 0..511
            int m  = q >> 2;                 // 0..127 (BK/4 = 4 quads per row)
            int kq = q & 3;                  // 0..3
            float4 v = *reinterpret_cast<const float4*>(
                A + (size_t)(row0 + m) * K + k0 + kq * 4);
            As[kq * 4 + 0][m] = v.x;
            As[kq * 4 + 1][m] = v.y;
            As[kq * 4 + 2][m] = v.z;
            As[kq * 4 + 3][m] = v.w;
        }
        // --- load B tile: BK*BN/4 = 256 quads, 1 per thread ---
        {
            int kr  = tid >> 4;              // 0..15
            int nq  = tid & 15;              // 0..15
            int col = col0 + nq * 4;
            float4 v;
            if (col + 3 < N) {
                v = *reinterpret_cast<const float4*>(
                    Bm + (size_t)(k0 + kr) * N + col);
            } else {
                v.x = (col + 0 < N) ? Bm[(size_t)(k0 + kr) * N + col + 0] : 0.0f;
                v.y = (col + 1 < N) ? Bm[(size_t)(k0 + kr) * N + col + 1] : 0.0f;
                v.z = (col + 2 < N) ? Bm[(size_t)(k0 + kr) * N + col + 2] : 0.0f;
                v.w = (col + 3 < N) ? Bm[(size_t)(k0 + kr) * N + col + 3] : 0.0f;
            }
            *reinterpret_cast<float4*>(&Bs[kr][nq * 4]) = v;
        }
        __syncthreads();

#pragma unroll
        for (int k = 0; k < BK; k++) {
            float a[TM], bb[TN];
#pragma unroll
            for (int i = 0; i < TM; i++) a[i] = As[k][ty * TM + i];
#pragma unroll
            for (int j = 0; j < TN; j++) bb[j] = Bs[k][tx * TN + j];
#pragma unroll
            for (int i = 0; i < TM; i++)
#pragma unroll
                for (int j = 0; j < TN; j++)
                    acc[i][j] += a[i] * bb[j];
        }
        __syncthreads();
    }

    // --- epilogue: add bias, bounded store ---
#pragma unroll
    for (int i = 0; i < TM; i++) {
        int row = row0 + ty * TM + i;
#pragma unroll
        for (int j = 0; j < TN; j++) {
            int col = col0 + tx * TN + j;
            if (col < N)
                C[(size_t)row * N + col] = acc[i][j] + bias[col];
        }
    }
}

// ---------------------------------------------------------------------------
// Launch: 5 kernels, graph-capturable, allocation-free.
// Inputs (metadata order):
//   0 tokens(int32 [B,1]) 1 features(f32 [B,E]) 2 hidden(unused)
//   3 emb(f32 [V,E])      4 gru_kernel(f32 [IN,3U]) 5 gru_rkernel(unused, h0=0)
//   6 gru_bias(f32 [2,3U]) 7 fc1_w(f32 [U,U]) 8 fc1_b 9 fc2_w(f32 [U,V]) 10 fc2_b
// Output: logits [B,V] then state [B,U], concatenated fp32.
// ---------------------------------------------------------------------------
extern "C" void kernel_launch(void* const* d_in, const int* in_sizes, int n_in,
                              void* d_out, int out_size) {
    const int*   tok  = (const int*)  d_in[0];
    const float* feat = (const float*)d_in[1];
    const float* emb  = (const float*)d_in[3];
    const float* gk   = (const float*)d_in[4];
    const float* gb   = (const float*)d_in[6];
    const float* f1w  = (const float*)d_in[7];
    const float* f1b  = (const float*)d_in[8];
    const float* f2w  = (const float*)d_in[9];
    const float* f2b  = (const float*)d_in[10];

    float* out    = (float*)d_out;
    float* logits = out;                               // [B, V]
    float* state  = out + (size_t)Bsz * Vv;            // [B, U]

    float *x_p, *gx_p, *y_p;
    cudaGetSymbolAddress((void**)&x_p,  g_x);
    cudaGetSymbolAddress((void**)&gx_p, g_gx);
    cudaGetSymbolAddress((void**)&y_p,  g_y);

    // 1) x = concat(features, emb[tokens])
    build_x_kernel<<<Bsz, 256>>>(tok, feat, emb);

    // 2) gx = x @ gru_kernel + gru_bias[0]       [8192,512]x[512,768]
    sgemm_bias_kernel<128, 64, 16, 8, 4>
        <<<dim3(Gdim / 64, Bsz / 128), 256>>>(x_p, gk, gb, gx_p, Bsz, Gdim, INdim);

    // 3) GRU gates -> h (state output)
    gru_gates_kernel<<<Bsz, 256>>>(gb, state);

    // 4) y = h @ fc1_w + fc1_b                   [8192,256]x[256,256]
    sgemm_bias_kernel<128, 64, 16, 8, 4>
        <<<dim3(Uh / 64, Bsz / 128), 256>>>(state, f1w, f1b, y_p, Bsz, Uh, Uh);

    // 5) logits = y @ fc2_w + fc2_b              [8192,256]x[256,4000]
    sgemm_bias_kernel<128, 64, 16, 8, 4>
        <<<dim3((Vv + 63) / 64, Bsz / 128), 256>>>(y_p, f2w, f2b, logits, Bsz, Vv, Uh);
}

// round 3
// speedup vs baseline: 1.9535x; 1.9535x over previous
#include <cuda_runtime.h>
#include <cuda_bf16.h>
#include <cstdint>
#include <math.h>

// ---------------- problem constants ----------------
#define Bsz   8192
#define Ein   256
#define Uh    256
#define Vv    4000
#define Gdim  768
#define KP1   1536            // 3*512 augmented K for GRU gemm
#define KP2   768             // 3*256 augmented K for fc1/fc2
#define NPAD2 4096            // fc2 N padded to multiple of 128

// ---------------- scratch (__device__, no allocs) ----------------
__device__ float          g_gx   [(size_t)Bsz * Gdim];
__device__ __nv_bfloat16  g_Aaug1[(size_t)Bsz * KP1];
__device__ __nv_bfloat16  g_Haug [(size_t)Bsz * KP2];
__device__ __nv_bfloat16  g_Yaug [(size_t)Bsz * KP2];
__device__ __nv_bfloat16  g_Bg   [(size_t)Gdim * KP1];
__device__ __nv_bfloat16  g_B1   [(size_t)Uh   * KP2];
__device__ __nv_bfloat16  g_B2   [(size_t)NPAD2* KP2];

// ---------------- helpers ----------------
__device__ __forceinline__ uint32_t smem_u32(const void* p) {
    uint32_t a;
    asm("{ .reg .u64 t; cvta.to.shared.u64 t, %1; cvt.u32.u64 %0, t; }" : "=r"(a) : "l"(p));
    return a;
}
__device__ __forceinline__ void cp16(uint32_t dst, const void* src) {
    asm volatile("cp.async.cg.shared.global [%0], [%1], 16;\n" :: "r"(dst), "l"(src));
}
__device__ __forceinline__ void ldsm4(uint32_t* r, uint32_t addr) {
    asm volatile("ldmatrix.sync.aligned.m8n8.x4.shared.b16 {%0,%1,%2,%3}, [%4];"
        : "=r"(r[0]), "=r"(r[1]), "=r"(r[2]), "=r"(r[3]) : "r"(addr));
}
__device__ __forceinline__ void mma16816(float* c, const uint32_t* a, const uint32_t* b) {
    asm volatile("mma.sync.aligned.m16n8k16.row.col.f32.bf16.bf16.f32 "
        "{%0,%1,%2,%3}, {%4,%5,%6,%7}, {%8,%9}, {%0,%1,%2,%3};"
        : "+f"(c[0]), "+f"(c[1]), "+f"(c[2]), "+f"(c[3])
        : "r"(a[0]), "r"(a[1]), "r"(a[2]), "r"(a[3]), "r"(b[0]), "r"(b[1]));
}
__device__ __forceinline__ void split_bf16(float v, __nv_bfloat16& hi, __nv_bfloat16& lo) {
    hi = __float2bfloat16_rn(v);
    lo = __float2bfloat16_rn(v - __bfloat162float(hi));
}

// ---------------- prep kernels ----------------
__global__ void build_aaug_kernel(const int* __restrict__ tok,
                                  const float* __restrict__ feat,
                                  const float* __restrict__ emb) {
    int b = blockIdx.x, c = threadIdx.x;
    int t = tok[b];
    size_t base = (size_t)b * KP1;
    float v0 = feat[(size_t)b * Ein + c];
    float v1 = emb[(size_t)t * Ein + c];
    __nv_bfloat16 h0, l0, h1, l1;
    split_bf16(v0, h0, l0);
    split_bf16(v1, h1, l1);
    g_Aaug1[base + c]              = h0;
    g_Aaug1[base + 512 + c]        = l0;
    g_Aaug1[base + 1024 + c]       = h0;
    g_Aaug1[base + 256 + c]        = h1;
    g_Aaug1[base + 512 + 256 + c]  = l1;
    g_Aaug1[base + 1024 + 256 + c] = h1;
}

// W[K,N] fp32 -> Baug[Npad, 3K] bf16 = [Bhi | Bhi | Blo] per row n
__global__ void split_wT_kernel(const float* __restrict__ W, __nv_bfloat16* __restrict__ Baug,
                                int K, int N, int Npad) {
    int idx = blockIdx.x * 256 + threadIdx.x;
    if (idx >= Npad * K) return;
    int n = idx / K, k = idx - n * K;
    float v = (n < N) ? W[(size_t)k * N + n] : 0.0f;
    __nv_bfloat16 hi, lo;
    split_bf16(v, hi, lo);
    size_t base = (size_t)n * (3 * K);
    Baug[base + k]         = hi;
    Baug[base + K + k]     = hi;
    Baug[base + 2 * K + k] = lo;
}

// GRU gates: h0==0 so recurrent term is just gru_bias[1].
__global__ void gru_gates_kernel(const float* __restrict__ gru_bias, float* __restrict__ state) {
    int b = blockIdx.x, u = threadIdx.x;
    const float* gx = g_gx + (size_t)b * Gdim;
    const float* b1 = gru_bias + Gdim;
    float z = 1.0f / (1.0f + expf(-(gx[u] + b1[u])));
    float r = 1.0f / (1.0f + expf(-(gx[256 + u] + b1[256 + u])));
    float n = tanhf(gx[512 + u] + r * b1[512 + u]);
    float h = (1.0f - z) * n;
    state[(size_t)b * Uh + u] = h;
    __nv_bfloat16 hi, lo;
    split_bf16(h, hi, lo);
    size_t base = (size_t)b * KP2;
    g_Haug[base + u]       = hi;
    g_Haug[base + 256 + u] = lo;
    g_Haug[base + 512 + u] = hi;
}

// ---------------- mma.sync bf16 GEMM ----------------
// C[M,N] = A[M,K'] @ B[N,K']^T + bias.  CTA tile 128x128, K chunks of 32 bf16.
// 8 warps: warp_m = wid&3 (32 rows), warp_n = wid>>2 (64 cols).
// SMEM: padded rows of 40 bf16 (80B) -> conflict-free ldmatrix & stores.
// MODE 0: fp32 out (bounds Nbound, stride ldC). MODE 1: bf16 aug out [hi|lo|hi].
template <int MODE>
__global__ void __launch_bounds__(256)
mma_gemm_kernel(const __nv_bfloat16* __restrict__ A, const __nv_bfloat16* __restrict__ B,
                const float* __restrict__ bias, float* __restrict__ Cf,
                __nv_bfloat16* __restrict__ Caug, int Kp, int ldC, int Nbound) {
    __shared__ __align__(16) __nv_bfloat16 sA[2][128 * 40];
    __shared__ __align__(16) __nv_bfloat16 sB[2][128 * 40];

    const int tid  = threadIdx.x;
    const int wid  = tid >> 5;
    const int lane = tid & 31;
    const int warp_m = wid & 3;
    const int warp_n = wid >> 2;
    const int row0 = blockIdx.y * 128;
    const int col0 = blockIdx.x * 128;

    const uint32_t sA_addr = smem_u32(&sA[0][0]);
    const uint32_t sB_addr = smem_u32(&sB[0][0]);

    const int NCH = Kp >> 5;          // chunks of 32 bf16

    // per-thread load mapping (2 x 16B per operand per chunk)
    const int lr = tid >> 2;          // rows lr, lr+64
    const int ls = tid & 3;           // 16B segment

    // per-lane ldmatrix offsets
    const uint32_t a_off = (uint32_t)(warp_m * 32 + (lane & 15)) * 80 + ((lane >> 4) * 16);
    const uint32_t b_off = (uint32_t)(warp_n * 64 + (lane & 7) + ((lane & 16) >> 1)) * 80
                         + (((lane >> 3) & 1) * 16);

    float acc[2][8][4];
#pragma unroll
    for (int t = 0; t < 2; t++)
#pragma unroll
        for (int n = 0; n < 8; n++)
#pragma unroll
            for (int j = 0; j < 4; j++) acc[t][n][j] = 0.0f;

    // prefetch chunk 0
    {
#pragma unroll
        for (int l = 0; l < 2; l++) {
            int r = lr + l * 64;
            cp16(sA_addr + r * 80 + ls * 16, A + (size_t)(row0 + r) * Kp + ls * 8);
            cp16(sB_addr + r * 80 + ls * 16, B + (size_t)(col0 + r) * Kp + ls * 8);
        }
        asm volatile("cp.async.commit_group;\n" ::: "memory");
    }

    for (int c = 0; c < NCH; c++) {
        if (c + 1 < NCH) {
            const int nb = (c + 1) & 1;
            const int kb = (c + 1) * 32;
#pragma unroll
            for (int l = 0; l < 2; l++) {
                int r = lr + l * 64;
                cp16(sA_addr + nb * 10240 + r * 80 + ls * 16,
                     A + (size_t)(row0 + r) * Kp + kb + ls * 8);
                cp16(sB_addr + nb * 10240 + r * 80 + ls * 16,
                     B + (size_t)(col0 + r) * Kp + kb + ls * 8);
            }
            asm volatile("cp.async.commit_group;\n" ::: "memory");
            asm volatile("cp.async.wait_group 1;\n" ::: "memory");
        } else {
            asm volatile("cp.async.wait_group 0;\n" ::: "memory");
        }
        __syncthreads();

        const uint32_t aBase = sA_addr + (c & 1) * 10240 + a_off;
        const uint32_t bBase = sB_addr + (c & 1) * 10240 + b_off;
#pragma unroll
        for (int ks = 0; ks < 2; ks++) {
            uint32_t af[2][4];
            ldsm4(af[0], aBase + ks * 32);
            ldsm4(af[1], aBase + 16 * 80 + ks * 32);
            uint32_t bf[8][2];
#pragma unroll
            for (int p = 0; p < 4; p++) {
                uint32_t tmp[4];
                ldsm4(tmp, bBase + p * 16 * 80 + ks * 32);
                bf[2 * p][0]     = tmp[0];
                bf[2 * p][1]     = tmp[1];
                bf[2 * p + 1][0] = tmp[2];
                bf[2 * p + 1][1] = tmp[3];
            }
#pragma unroll
            for (int t = 0; t < 2; t++)
#pragma unroll
                for (int n = 0; n < 8; n++)
                    mma16816(acc[t][n], af[t], bf[n]);
        }
        __syncthreads();
    }

    // epilogue
    const int er = row0 + warp_m * 32 + (lane >> 2);
    const int ec = col0 + warp_n * 64 + (lane & 3) * 2;
#pragma unroll
    for (int t = 0; t < 2; t++) {
#pragma unroll
        for (int n = 0; n < 8; n++) {
            const int col = ec + n * 8;
#pragma unroll
            for (int half = 0; half < 2; half++) {
                const int row = er + t * 16 + half * 8;
                const float v0 = acc[t][n][2 * half + 0];
                const float v1 = acc[t][n][2 * half + 1];
                if (MODE == 0) {
                    if (col < Nbound) {
                        float2 o;
                        o.x = v0 + bias[col];
                        o.y = v1 + bias[col + 1];
                        *reinterpret_cast<float2*>(Cf + (size_t)row * ldC + col) = o;
                    }
                } else {
                    float w0 = v0 + bias[col];
                    float w1 = v1 + bias[col + 1];
                    __nv_bfloat16 h0, l0, h1, l1;
                    split_bf16(w0, h0, l0);
                    split_bf16(w1, h1, l1);
                    size_t rb = (size_t)row * KP2;
                    Caug[rb + col]           = h0;
                    Caug[rb + col + 1]       = h1;
                    Caug[rb + 256 + col]     = l0;
                    Caug[rb + 256 + col + 1] = l1;
                    Caug[rb + 512 + col]     = h0;
                    Caug[rb + 512 + col + 1] = h1;
                }
            }
        }
    }
}

// ---------------- launch ----------------
extern "C" void kernel_launch(void* const* d_in, const int* in_sizes, int n_in,
                              void* d_out, int out_size) {
    const int*   tok  = (const int*)  d_in[0];
    const float* feat = (const float*)d_in[1];
    const float* emb  = (const float*)d_in[3];
    const float* gk   = (const float*)d_in[4];
    const float* gb   = (const float*)d_in[6];
    const float* f1w  = (const float*)d_in[7];
    const float* f1b  = (const float*)d_in[8];
    const float* f2w  = (const float*)d_in[9];
    const float* f2b  = (const float*)d_in[10];

    float* out    = (float*)d_out;
    float* logits = out;                               // [B, V]
    float* state  = out + (size_t)Bsz * Vv;            // [B, U]

    float *gx_p; __nv_bfloat16 *aaug_p, *haug_p, *yaug_p, *bg_p, *b1_p, *b2_p;
    cudaGetSymbolAddress((void**)&gx_p,   g_gx);
    cudaGetSymbolAddress((void**)&aaug_p, g_Aaug1);
    cudaGetSymbolAddress((void**)&haug_p, g_Haug);
    cudaGetSymbolAddress((void**)&yaug_p, g_Yaug);
    cudaGetSymbolAddress((void**)&bg_p,   g_Bg);
    cudaGetSymbolAddress((void**)&b1_p,   g_B1);
    cudaGetSymbolAddress((void**)&b2_p,   g_B2);

    // operand prep
    build_aaug_kernel<<<Bsz, 256>>>(tok, feat, emb);
    split_wT_kernel<<<(Gdim * 512 + 255) / 256, 256>>>(gk,  bg_p, 512, Gdim, Gdim);
    split_wT_kernel<<<(Uh * 256 + 255) / 256,  256>>>(f1w, b1_p, 256, Uh, Uh);
    split_wT_kernel<<<(NPAD2 * 256 + 255) / 256, 256>>>(f2w, b2_p, 256, Vv, NPAD2);

    // 1) gx = x @ gru_kernel + gru_bias[0]   [8192,1536aug] x [768,1536aug]^T
    mma_gemm_kernel<0><<<dim3(Gdim / 128, Bsz / 128), 256>>>(
        aaug_p, bg_p, gb, gx_p, nullptr, KP1, Gdim, Gdim);

    // 2) gates -> state (f32, into d_out) + Haug
    gru_gates_kernel<<<Bsz, 256>>>(gb, state);

    // 3) yaug = split(h @ fc1_w + fc1_b)     [8192,768aug] x [256,768aug]^T
    mma_gemm_kernel<1><<<dim3(Uh / 128, Bsz / 128), 256>>>(
        haug_p, b1_p, f1b, nullptr, yaug_p, KP2, Uh, Uh);

    // 4) logits = y @ fc2_w + fc2_b          [8192,768aug] x [4096,768aug]^T
    mma_gemm_kernel<0><<<dim3(NPAD2 / 128, Bsz / 128), 256>>>(
        yaug_p, b2_p, f2b, logits, nullptr, KP2, Vv, Vv);
}